// round 16
// baseline (speedup 1.0000x reference)
#include <cuda_runtime.h>

// ---------------- problem constants ----------------
#define NB      65536          // batch
#define IN2     256
#define H2      512
#define NA      32
#define QSIZE   (2*NB*NA)      // q elements in d_out before h

// ---------------- device scratch (no allocs allowed) ----------------
__device__ __align__(16) float g_X  [ (size_t)NB * H2 ];    // rounded relu(fc1)
__device__ __align__(16) float g_Hr [ (size_t)NB * H2 ];    // rounded hidden
__device__ __align__(16) float g_Grz[ (size_t)NB * 1024 ];  // raw r,z gate pre-activations (interleaved per j)
__device__ __align__(16) float g_NN [ (size_t)NB * 1024 ];  // raw [in(512) | hn(512)] pre-activations
__device__ __align__(16) float g_Wrz[ 1024 * 1024 ];        // packed+rounded r,z weights [n=2j+g][k=1024]
__device__ __align__(16) float g_Wnn[ 1024 * 512 ];         // rows 0..511: Win (over X); 512..1023: Whn (over Hr)
__device__ __align__(16) float g_W2 [ 64 * 512 ];           // packed+rounded W21|W22
__device__ __align__(16) float g_b2 [ 64 ];                 // packed b21|b22

// ---------------- helpers ----------------
__device__ __forceinline__ unsigned f2tf(float x) {
    unsigned u;
    asm("cvt.rna.tf32.f32 %0, %1;" : "=r"(u) : "f"(x));
    return u;
}
__device__ __forceinline__ float f2tf_f(float x) { return __uint_as_float(f2tf(x)); }

__device__ __forceinline__ void mma8(float* c, const unsigned* a, const unsigned* b) {
    asm volatile(
        "mma.sync.aligned.m16n8k8.row.col.f32.tf32.tf32.f32 "
        "{%0,%1,%2,%3}, {%4,%5,%6,%7}, {%8,%9}, {%0,%1,%2,%3};"
        : "+f"(c[0]), "+f"(c[1]), "+f"(c[2]), "+f"(c[3])
        : "r"(a[0]), "r"(a[1]), "r"(a[2]), "r"(a[3]), "r"(b[0]), "r"(b[1]));
}

#define LDSM_X4(r0, r1, r2, r3, addr) \
    asm volatile("ldmatrix.sync.aligned.m8n8.x4.shared.b16 {%0,%1,%2,%3}, [%4];" \
        : "=r"(r0), "=r"(r1), "=r"(r2), "=r"(r3) : "r"(addr))

__device__ __forceinline__ float sigmoidf_(float x) {
    return 1.f / (1.f + __expf(-x));
}
__device__ __forceinline__ float tanhf_(float x) {
    float t = __expf(-2.f * fabsf(x));
    float r = (1.f - t) / (1.f + t);
    return copysignf(r, x);
}
__device__ __forceinline__ unsigned smem_u32p(const void* p) {
    unsigned a;
    asm("{ .reg .u64 t; cvta.to.shared.u64 t, %1; cvt.u32.u64 %0, t; }" : "=r"(a) : "l"(p));
    return a;
}

// ---------------- weight pack kernel (split-gate layout, rounded; validated) ----------------
__global__ void pack_kernel(const float* __restrict__ W_ih, const float* __restrict__ W_hh,
                            const float* __restrict__ W21,  const float* __restrict__ W22,
                            const float* __restrict__ b21,  const float* __restrict__ b22) {
    int idx = blockIdx.x * 256 + threadIdx.x;           // [0, 1024*1024)
    {
        int n = idx >> 10, k = idx & 1023;
        int j = n >> 1, g = n & 1;
        float v = (k < 512) ? W_ih[(g * 512 + j) * 512 + k]
                            : W_hh[(g * 512 + j) * 512 + (k - 512)];
        g_Wrz[idx] = f2tf_f(v);
    }
    if (idx < 1024 * 512) {
        int n = idx >> 9, k = idx & 511;
        float v = (n < 512) ? W_ih[(1024 + n) * 512 + k]
                            : W_hh[(1024 + (n - 512)) * 512 + k];
        g_Wnn[idx] = f2tf_f(v);
    }
    if (idx < 64 * 512) {
        int n2 = idx >> 9, k2 = idx & 511;
        g_W2[idx] = f2tf_f((n2 < 32) ? W21[n2 * 512 + k2] : W22[(n2 - 32) * 512 + k2]);
    }
    if (idx < 64) g_b2[idx] = (idx < 32) ? b21[idx] : b22[idx - 32];
}

// ---------------- hidden rounding kernel (R10-validated) ----------------
__global__ void roundH_kernel(const float* __restrict__ hidden) {
    size_t t = (size_t)blockIdx.x * 256 + threadIdx.x;   // float4 index, total NB*128
    float4 v = ((const float4*)hidden)[t];
    v.x = f2tf_f(v.x); v.y = f2tf_f(v.y); v.z = f2tf_f(v.z); v.w = f2tf_f(v.w);
    ((float4*)g_Hr)[t] = v;
}

// ---------------- GRU combine (R9/R10-validated) ----------------
__global__ void gru_combine(const float* __restrict__ Grz, const float* __restrict__ NN,
                            const float* __restrict__ hidden,
                            const float* __restrict__ b_ih, const float* __restrict__ b_hh,
                            float* __restrict__ outH) {
    size_t e = (size_t)blockIdx.x * 256 + threadIdx.x;   // [0, NB*256)
    int row = (int)(e >> 8);
    int j   = (int)(e & 255) * 2;                        // handles j and j+1
    float4 rz  = *(const float4*)(Grz    + (size_t)row * 1024 + 2 * j);
    float2 in2 = *(const float2*)(NN     + (size_t)row * 1024 + j);
    float2 hn2 = *(const float2*)(NN     + (size_t)row * 1024 + 512 + j);
    float2 hi2 = *(const float2*)(hidden + (size_t)row * 512  + j);
    float2 o;
    {
        float r = sigmoidf_(rz.x + b_ih[j] + b_hh[j]);
        float z = sigmoidf_(rz.y + b_ih[512 + j] + b_hh[512 + j]);
        float n = tanhf_(in2.x + b_ih[1024 + j] + r * (hn2.x + b_hh[1024 + j]));
        o.x = f2tf_f((1.f - z) * n + z * hi2.x);
    }
    {
        int j1 = j + 1;
        float r = sigmoidf_(rz.z + b_ih[j1] + b_hh[j1]);
        float z = sigmoidf_(rz.w + b_ih[512 + j1] + b_hh[512 + j1]);
        float n = tanhf_(in2.y + b_ih[1024 + j1] + r * (hn2.y + b_hh[1024 + j1]));
        o.y = f2tf_f((1.f - z) * n + z * hi2.y);
    }
    *(float2*)(outH + (size_t)row * 512 + j) = o;
}

// ---------------- tiled tf32 GEMM: BMT x BN CTA tile, 64-col warp tiles (R10-validated) ----------------
// C[BMT x BN] = A[.,Ktot] @ W[N,Ktot]^T
// BMT 256: 4 warps x 64 rows (R10 shape, occ 1); BMT 128: 4 warps x 32 rows (R9 shape, occ 2).
// ASEL 0: A element (r,k) = k < ksplit ? Alo[r*ldA+k] : Ahi[r*ldA+(k-ksplit)]
// ASEL 1: A = (n0 < ksplit) ? Alo : Ahi, k used directly (per-n-block A selection)
// DOCVT: round operands to tf32 while storing to smem (free at occ 2; costs alu at occ 1).
// EPI 0: out = round(relu(acc + bias0)),  EPI 1: out = acc + bias0,  EPI 3: out = acc (raw).
template<int BMT, int BN, int EPI, bool DOCVT, int ASEL, int OCC>
__global__ void __launch_bounds__(256, OCC)
gemm_tf32(const float* __restrict__ Alo, const float* __restrict__ Ahi,
          int ldA, int ksplit, int Ktot,
          const float* __restrict__ W, int ldW,
          const float* __restrict__ bias0,
          float* __restrict__ out, int ldOut)
{
    constexpr int MI  = BMT / 64;     // 16-row m-fragments per warp (256->4, 128->2)
    constexpr int NF  = BN / 16;      // n-fragments per warp (warp covers BN/2 cols)
    constexpr int NP  = NF / 2;       // ldmatrix.x4 pairs for B
    constexpr int NA4 = BMT / 32;     // A float4 per thread per tile
    constexpr int NB4 = BN / 32;      // B float4 per thread per tile

    extern __shared__ unsigned smem_u[];
    unsigned* As = smem_u;                     // [2][BMT*36]
    unsigned* Bs = smem_u + 2 * BMT * 36;      // [2][BN*36]

    const int tid  = threadIdx.x;
    const int lane = tid & 31;
    const int warp = tid >> 5;
    const int g    = lane >> 2;               // groupID
    const int tg   = lane & 3;                // threadID_in_group
    const int wM   = warp & 3;                // 4 warps along M (MI*16 rows each)
    const int wN   = warp >> 2;               // 2 warps along N (BN/2 each)
    const int m0   = blockIdx.y * BMT;
    const int n0   = blockIdx.x * BN;

    const unsigned sAbase = smem_u32p(As);
    const unsigned sBbase = smem_u32p(Bs);
    unsigned aAddr[MI], bAddr[NP];
    #pragma unroll
    for (int mi = 0; mi < MI; mi++) {
        int row = wM * (MI * 16) + mi * 16 + (lane & 15);
        int col = 4 * (lane >> 4);
        aAddr[mi] = sAbase + (unsigned)(row * 36 + col) * 4u;
    }
    #pragma unroll
    for (int pi = 0; pi < NP; pi++) {
        int row = wN * (BN / 2) + pi * 16 + (lane & 7) + 8 * (lane >> 4);
        int col = 4 * ((lane >> 3) & 1);
        bAddr[pi] = sBbase + (unsigned)(row * 36 + col) * 4u;
    }

    float acc[MI][NF][4];
    #pragma unroll
    for (int mi = 0; mi < MI; mi++)
        #pragma unroll
        for (int ni = 0; ni < NF; ni++)
            #pragma unroll
            for (int q = 0; q < 4; q++) acc[mi][ni][q] = 0.f;

    const int rb = tid >> 3;          // loader row base (row = rb + 32*i)
    const int c4 = tid & 7;           // 16B column chunk

    float4 pa[NA4], pb[NB4];
    auto loadGlobal = [&](int k0) {
        const float* Ap; int koff;
        if (ASEL == 1)        { Ap = (n0 < ksplit) ? Alo : Ahi; koff = k0; }
        else if (k0 < ksplit) { Ap = Alo; koff = k0; }
        else                  { Ap = Ahi; koff = k0 - ksplit; }
        #pragma unroll
        for (int i = 0; i < NA4; i++) {
            int r = rb + 32 * i;
            pa[i] = *(const float4*)(Ap + (size_t)(m0 + r) * ldA + koff + c4 * 4);
        }
        #pragma unroll
        for (int i = 0; i < NB4; i++) {
            int r = rb + 32 * i;
            pb[i] = *(const float4*)(W + (size_t)(n0 + r) * ldW + k0 + c4 * 4);
        }
    };
    auto storeSmem = [&](int buf) {
        unsigned* Ab = As + buf * BMT * 36;
        unsigned* Bb = Bs + buf * BN * 36;
        #pragma unroll
        for (int i = 0; i < NA4; i++) {
            int r = rb + 32 * i;
            uint4 u;
            if (DOCVT) {
                u.x = f2tf(pa[i].x); u.y = f2tf(pa[i].y);
                u.z = f2tf(pa[i].z); u.w = f2tf(pa[i].w);
            } else {
                u = *(const uint4*)&pa[i];
            }
            *(uint4*)(Ab + r * 36 + c4 * 4) = u;
        }
        #pragma unroll
        for (int i = 0; i < NB4; i++) {
            int r = rb + 32 * i;
            uint4 u;
            if (DOCVT) {
                u.x = f2tf(pb[i].x); u.y = f2tf(pb[i].y);
                u.z = f2tf(pb[i].z); u.w = f2tf(pb[i].w);
            } else {
                u = *(const uint4*)&pb[i];
            }
            *(uint4*)(Bb + r * 36 + c4 * 4) = u;
        }
    };

    auto compute = [&](int buf) {
        const unsigned aOff = (unsigned)(buf * BMT * 36) * 4u;
        const unsigned bOff = (unsigned)(buf * BN * 36) * 4u;
        #pragma unroll
        for (int ks = 0; ks < 4; ks++) {
            const unsigned kOff = (unsigned)ks * 32u;   // 8 tf32 cols = 32 bytes
            unsigned af[MI][4];
            #pragma unroll
            for (int mi = 0; mi < MI; mi++)
                LDSM_X4(af[mi][0], af[mi][1], af[mi][2], af[mi][3],
                        aAddr[mi] + aOff + kOff);
            unsigned bf[NF][2];
            #pragma unroll
            for (int pi = 0; pi < NP; pi++)
                LDSM_X4(bf[2 * pi][0], bf[2 * pi][1], bf[2 * pi + 1][0], bf[2 * pi + 1][1],
                        bAddr[pi] + bOff + kOff);
            #pragma unroll
            for (int mi = 0; mi < MI; mi++)
                #pragma unroll
                for (int ni = 0; ni < NF; ni++)
                    mma8(acc[mi][ni], af[mi], bf[ni]);
        }
    };

    // ---- mainloop: double-buffered, one barrier per K-iter (R10-validated) ----
    loadGlobal(0);
    storeSmem(0);
    __syncthreads();
    const int kIters = Ktot / 32;
    for (int it = 0; it < kIters; ++it) {
        if (it + 1 < kIters) loadGlobal((it + 1) * 32);
        compute(it & 1);
        if (it + 1 < kIters) storeSmem((it + 1) & 1);
        __syncthreads();
    }

    // ---- epilogue ----
    #pragma unroll
    for (int mi = 0; mi < MI; mi++) {
        #pragma unroll
        for (int ni = 0; ni < NF; ni++) {
            int row = m0 + wM * (MI * 16) + mi * 16 + g;
            int col = n0 + wN * (BN / 2) + ni * 8 + 2 * tg;
            float v0 = acc[mi][ni][0], v1 = acc[mi][ni][1];
            float v2 = acc[mi][ni][2], v3 = acc[mi][ni][3];
            if (EPI == 0 || EPI == 1) {
                float bv0 = bias0[col], bv1 = bias0[col + 1];
                v0 += bv0; v1 += bv1; v2 += bv0; v3 += bv1;
            }
            if (EPI == 0) {
                // X feeds later GEMMs via raw copies -> store rounded
                v0 = f2tf_f(fmaxf(v0, 0.f)); v1 = f2tf_f(fmaxf(v1, 0.f));
                v2 = f2tf_f(fmaxf(v2, 0.f)); v3 = f2tf_f(fmaxf(v3, 0.f));
            }
            *(float2*)(out + (size_t)row * ldOut + col)       = make_float2(v0, v1);
            *(float2*)(out + (size_t)(row + 8) * ldOut + col) = make_float2(v2, v3);
        }
    }
}

// ---------------- host launcher ----------------
extern "C" void kernel_launch(void* const* d_in, const int* in_sizes, int n_in,
                              void* d_out, int out_size) {
    const float* inputs = (const float*)d_in[0];
    const float* hidden = (const float*)d_in[1];
    const float* W1     = (const float*)d_in[2];
    const float* b1     = (const float*)d_in[3];
    const float* W_ih   = (const float*)d_in[4];
    const float* W_hh   = (const float*)d_in[5];
    const float* b_ih   = (const float*)d_in[6];
    const float* b_hh   = (const float*)d_in[7];
    const float* W21    = (const float*)d_in[8];
    const float* b21    = (const float*)d_in[9];
    const float* W22    = (const float*)d_in[10];
    const float* b22    = (const float*)d_in[11];

    float* outQ = (float*)d_out;
    float* outH = (float*)d_out + (size_t)QSIZE;

    void *pX, *pHr, *pGrz, *pNN, *pWrz, *pWnn, *pW2, *pb2;
    cudaGetSymbolAddress(&pX,   g_X);
    cudaGetSymbolAddress(&pHr,  g_Hr);
    cudaGetSymbolAddress(&pGrz, g_Grz);
    cudaGetSymbolAddress(&pNN,  g_NN);
    cudaGetSymbolAddress(&pWrz, g_Wrz);
    cudaGetSymbolAddress(&pWnn, g_Wnn);
    cudaGetSymbolAddress(&pW2,  g_W2);
    cudaGetSymbolAddress(&pb2,  g_b2);

    const int smemBig  = (2 * 256 * 36 + 2 * 128 * 36) * 4;   // 110592
    const int smemFc1  = (2 * 128 * 36 + 2 * 128 * 36) * 4;   //  73728
    const int smemHead = (2 * 128 * 36 + 2 *  64 * 36) * 4;   //  55296
    cudaFuncSetAttribute(gemm_tf32<128, 128, 0, true , 0, 2>, cudaFuncAttributeMaxDynamicSharedMemorySize, smemFc1);
    cudaFuncSetAttribute(gemm_tf32<256, 128, 3, false, 0, 1>, cudaFuncAttributeMaxDynamicSharedMemorySize, smemBig);
    cudaFuncSetAttribute(gemm_tf32<256, 128, 3, false, 1, 1>, cudaFuncAttributeMaxDynamicSharedMemorySize, smemBig);
    cudaFuncSetAttribute(gemm_tf32<128,  64, 1, false, 0, 2>, cudaFuncAttributeMaxDynamicSharedMemorySize, smemHead);

    // 0) pack + round split-gate weights; round hidden into g_Hr
    pack_kernel<<<(1024 * 1024) / 256, 256>>>(W_ih, W_hh, W21, W22, b21, b22);
    roundH_kernel<<<(NB * 128) / 256, 256>>>(hidden);

    // 1) X = round(relu(inputs @ W1^T + b1))   [B,512], K=256
    //    R9-validated 128-tile occ-2 engine: cvt is free at 16 warps/SM, clean wave packing.
    gemm_tf32<128, 128, 0, true, 0, 2><<<dim3(4, NB / 128), 256, smemFc1>>>(
        inputs, inputs, IN2, IN2, IN2,
        W1, IN2, b1, (float*)pX, H2);

    // 2a) G_rz = [X|Hr] @ Wrz^T   [B,1024], K=1024, raw store (pre-rounded, no cvt)
    gemm_tf32<256, 128, 3, false, 0, 1><<<dim3(8, NB / 256), 256, smemBig>>>(
        (const float*)pX, (const float*)pHr, H2, H2, 1024,
        (const float*)pWrz, 1024, nullptr, (float*)pGrz, 1024);

    // 2b+c) NN = [X@Win^T | Hr@Whn^T]   [B,1024], K=512, A per n-block, raw store
    gemm_tf32<256, 128, 3, false, 1, 1><<<dim3(8, NB / 256), 256, smemBig>>>(
        (const float*)pX, (const float*)pHr, H2, H2 /*n-threshold*/, H2,
        (const float*)pWnn, H2, nullptr, (float*)pNN, 1024);

    // 2d) combine gates -> h (rounded) into outH (reads raw hidden for h_in)
    gru_combine<<<(NB * 256) / 256, 256>>>(
        (const float*)pGrz, (const float*)pNN, hidden, b_ih, b_hh, outH);

    // 3) q = h @ [W21;W22]^T + b, interleaved == row-major [B,64]  (128-tile, 2 CTA/SM)
    gemm_tf32<128, 64, 1, false, 0, 2><<<dim3(1, NB / 128), 256, smemHead>>>(
        outH, outH, H2, H2, H2,
        (const float*)pW2, H2, (const float*)pb2, outQ, 64);
}

// round 17
// speedup vs baseline: 1.0373x; 1.0373x over previous
#include <cuda_runtime.h>

// ---------------- problem constants ----------------
#define NB      65536          // batch
#define IN2     256
#define H2      512
#define NA      32
#define QSIZE   (2*NB*NA)      // q elements in d_out before h

// ---------------- device scratch (no allocs allowed) ----------------
__device__ __align__(16) float g_X  [ (size_t)NB * H2 ];    // rounded relu(fc1)
__device__ __align__(16) float g_Hr [ (size_t)NB * H2 ];    // rounded hidden
__device__ __align__(16) float g_Grz[ (size_t)NB * 1024 ];  // raw r,z gate pre-activations (interleaved per j)
__device__ __align__(16) float g_NN [ (size_t)NB * 1024 ];  // raw [in(512) | hn(512)] pre-activations
__device__ __align__(16) float g_Wrz[ 1024 * 1024 ];        // packed+rounded r,z weights [n=2j+g][k=1024]
__device__ __align__(16) float g_Wnn[ 1024 * 512 ];         // rows 0..511: Win (over X); 512..1023: Whn (over Hr)
__device__ __align__(16) float g_W2 [ 64 * 512 ];           // packed+rounded W21|W22
__device__ __align__(16) float g_b2 [ 64 ];                 // packed b21|b22

// ---------------- helpers ----------------
__device__ __forceinline__ unsigned f2tf(float x) {
    unsigned u;
    asm("cvt.rna.tf32.f32 %0, %1;" : "=r"(u) : "f"(x));
    return u;
}
__device__ __forceinline__ float f2tf_f(float x) { return __uint_as_float(f2tf(x)); }

__device__ __forceinline__ void mma8(float* c, const unsigned* a, const unsigned* b) {
    asm volatile(
        "mma.sync.aligned.m16n8k8.row.col.f32.tf32.tf32.f32 "
        "{%0,%1,%2,%3}, {%4,%5,%6,%7}, {%8,%9}, {%0,%1,%2,%3};"
        : "+f"(c[0]), "+f"(c[1]), "+f"(c[2]), "+f"(c[3])
        : "r"(a[0]), "r"(a[1]), "r"(a[2]), "r"(a[3]), "r"(b[0]), "r"(b[1]));
}

#define LDSM_X4(r0, r1, r2, r3, addr) \
    asm volatile("ldmatrix.sync.aligned.m8n8.x4.shared.b16 {%0,%1,%2,%3}, [%4];" \
        : "=r"(r0), "=r"(r1), "=r"(r2), "=r"(r3) : "r"(addr))

__device__ __forceinline__ float sigmoidf_(float x) {
    return 1.f / (1.f + __expf(-x));
}
__device__ __forceinline__ float tanhf_(float x) {
    float t = __expf(-2.f * fabsf(x));
    float r = (1.f - t) / (1.f + t);
    return copysignf(r, x);
}
__device__ __forceinline__ unsigned smem_u32p(const void* p) {
    unsigned a;
    asm("{ .reg .u64 t; cvta.to.shared.u64 t, %1; cvt.u32.u64 %0, t; }" : "=r"(a) : "l"(p));
    return a;
}

// ---------------- weight pack kernel (split-gate layout, rounded; validated) ----------------
__global__ void pack_kernel(const float* __restrict__ W_ih, const float* __restrict__ W_hh,
                            const float* __restrict__ W21,  const float* __restrict__ W22,
                            const float* __restrict__ b21,  const float* __restrict__ b22) {
    int idx = blockIdx.x * 256 + threadIdx.x;           // [0, 1024*1024)
    {
        int n = idx >> 10, k = idx & 1023;
        int j = n >> 1, g = n & 1;
        float v = (k < 512) ? W_ih[(g * 512 + j) * 512 + k]
                            : W_hh[(g * 512 + j) * 512 + (k - 512)];
        g_Wrz[idx] = f2tf_f(v);
    }
    if (idx < 1024 * 512) {
        int n = idx >> 9, k = idx & 511;
        float v = (n < 512) ? W_ih[(1024 + n) * 512 + k]
                            : W_hh[(1024 + (n - 512)) * 512 + k];
        g_Wnn[idx] = f2tf_f(v);
    }
    if (idx < 64 * 512) {
        int n2 = idx >> 9, k2 = idx & 511;
        g_W2[idx] = f2tf_f((n2 < 32) ? W21[n2 * 512 + k2] : W22[(n2 - 32) * 512 + k2]);
    }
    if (idx < 64) g_b2[idx] = (idx < 32) ? b21[idx] : b22[idx - 32];
}

// ---------------- hidden rounding kernel (R10-validated) ----------------
__global__ void roundH_kernel(const float* __restrict__ hidden) {
    size_t t = (size_t)blockIdx.x * 256 + threadIdx.x;   // float4 index, total NB*128
    float4 v = ((const float4*)hidden)[t];
    v.x = f2tf_f(v.x); v.y = f2tf_f(v.y); v.z = f2tf_f(v.z); v.w = f2tf_f(v.w);
    ((float4*)g_Hr)[t] = v;
}

// ---------------- GRU combine (R9/R10-validated) ----------------
__global__ void gru_combine(const float* __restrict__ Grz, const float* __restrict__ NN,
                            const float* __restrict__ hidden,
                            const float* __restrict__ b_ih, const float* __restrict__ b_hh,
                            float* __restrict__ outH) {
    size_t e = (size_t)blockIdx.x * 256 + threadIdx.x;   // [0, NB*256)
    int row = (int)(e >> 8);
    int j   = (int)(e & 255) * 2;                        // handles j and j+1
    float4 rz  = *(const float4*)(Grz    + (size_t)row * 1024 + 2 * j);
    float2 in2 = *(const float2*)(NN     + (size_t)row * 1024 + j);
    float2 hn2 = *(const float2*)(NN     + (size_t)row * 1024 + 512 + j);
    float2 hi2 = *(const float2*)(hidden + (size_t)row * 512  + j);
    float2 o;
    {
        float r = sigmoidf_(rz.x + b_ih[j] + b_hh[j]);
        float z = sigmoidf_(rz.y + b_ih[512 + j] + b_hh[512 + j]);
        float n = tanhf_(in2.x + b_ih[1024 + j] + r * (hn2.x + b_hh[1024 + j]));
        o.x = f2tf_f((1.f - z) * n + z * hi2.x);
    }
    {
        int j1 = j + 1;
        float r = sigmoidf_(rz.z + b_ih[j1] + b_hh[j1]);
        float z = sigmoidf_(rz.w + b_ih[512 + j1] + b_hh[512 + j1]);
        float n = tanhf_(in2.y + b_ih[1024 + j1] + r * (hn2.y + b_hh[1024 + j1]));
        o.y = f2tf_f((1.f - z) * n + z * hi2.y);
    }
    *(float2*)(outH + (size_t)row * 512 + j) = o;
}

// ---------------- tiled tf32 GEMM (templated engine; fc1 + head use this) ----------------
// C[BMT x BN] = A[.,Ktot] @ W[N,Ktot]^T   (R10-validated)
template<int BMT, int BN, int EPI, bool DOCVT, int ASEL, int OCC>
__global__ void __launch_bounds__(256, OCC)
gemm_tf32(const float* __restrict__ Alo, const float* __restrict__ Ahi,
          int ldA, int ksplit, int Ktot,
          const float* __restrict__ W, int ldW,
          const float* __restrict__ bias0,
          float* __restrict__ out, int ldOut)
{
    constexpr int MI  = BMT / 64;
    constexpr int NF  = BN / 16;
    constexpr int NP  = NF / 2;
    constexpr int NA4 = BMT / 32;
    constexpr int NB4 = BN / 32;

    extern __shared__ unsigned smem_u[];
    unsigned* As = smem_u;
    unsigned* Bs = smem_u + 2 * BMT * 36;

    const int tid  = threadIdx.x;
    const int lane = tid & 31;
    const int warp = tid >> 5;
    const int g    = lane >> 2;
    const int tg   = lane & 3;
    const int wM   = warp & 3;
    const int wN   = warp >> 2;
    const int m0   = blockIdx.y * BMT;
    const int n0   = blockIdx.x * BN;

    const unsigned sAbase = smem_u32p(As);
    const unsigned sBbase = smem_u32p(Bs);
    unsigned aAddr[MI], bAddr[NP];
    #pragma unroll
    for (int mi = 0; mi < MI; mi++) {
        int row = wM * (MI * 16) + mi * 16 + (lane & 15);
        int col = 4 * (lane >> 4);
        aAddr[mi] = sAbase + (unsigned)(row * 36 + col) * 4u;
    }
    #pragma unroll
    for (int pi = 0; pi < NP; pi++) {
        int row = wN * (BN / 2) + pi * 16 + (lane & 7) + 8 * (lane >> 4);
        int col = 4 * ((lane >> 3) & 1);
        bAddr[pi] = sBbase + (unsigned)(row * 36 + col) * 4u;
    }

    float acc[MI][NF][4];
    #pragma unroll
    for (int mi = 0; mi < MI; mi++)
        #pragma unroll
        for (int ni = 0; ni < NF; ni++)
            #pragma unroll
            for (int q = 0; q < 4; q++) acc[mi][ni][q] = 0.f;

    const int rb = tid >> 3;
    const int c4 = tid & 7;

    float4 pa[NA4], pb[NB4];
    auto loadGlobal = [&](int k0) {
        const float* Ap; int koff;
        if (ASEL == 1)        { Ap = (n0 < ksplit) ? Alo : Ahi; koff = k0; }
        else if (k0 < ksplit) { Ap = Alo; koff = k0; }
        else                  { Ap = Ahi; koff = k0 - ksplit; }
        #pragma unroll
        for (int i = 0; i < NA4; i++) {
            int r = rb + 32 * i;
            pa[i] = *(const float4*)(Ap + (size_t)(m0 + r) * ldA + koff + c4 * 4);
        }
        #pragma unroll
        for (int i = 0; i < NB4; i++) {
            int r = rb + 32 * i;
            pb[i] = *(const float4*)(W + (size_t)(n0 + r) * ldW + k0 + c4 * 4);
        }
    };
    auto storeSmem = [&](int buf) {
        unsigned* Ab = As + buf * BMT * 36;
        unsigned* Bb = Bs + buf * BN * 36;
        #pragma unroll
        for (int i = 0; i < NA4; i++) {
            int r = rb + 32 * i;
            uint4 u;
            if (DOCVT) {
                u.x = f2tf(pa[i].x); u.y = f2tf(pa[i].y);
                u.z = f2tf(pa[i].z); u.w = f2tf(pa[i].w);
            } else {
                u = *(const uint4*)&pa[i];
            }
            *(uint4*)(Ab + r * 36 + c4 * 4) = u;
        }
        #pragma unroll
        for (int i = 0; i < NB4; i++) {
            int r = rb + 32 * i;
            uint4 u;
            if (DOCVT) {
                u.x = f2tf(pb[i].x); u.y = f2tf(pb[i].y);
                u.z = f2tf(pb[i].z); u.w = f2tf(pb[i].w);
            } else {
                u = *(const uint4*)&pb[i];
            }
            *(uint4*)(Bb + r * 36 + c4 * 4) = u;
        }
    };

    auto compute = [&](int buf) {
        const unsigned aOff = (unsigned)(buf * BMT * 36) * 4u;
        const unsigned bOff = (unsigned)(buf * BN * 36) * 4u;
        #pragma unroll
        for (int ks = 0; ks < 4; ks++) {
            const unsigned kOff = (unsigned)ks * 32u;
            unsigned af[MI][4];
            #pragma unroll
            for (int mi = 0; mi < MI; mi++)
                LDSM_X4(af[mi][0], af[mi][1], af[mi][2], af[mi][3],
                        aAddr[mi] + aOff + kOff);
            unsigned bf[NF][2];
            #pragma unroll
            for (int pi = 0; pi < NP; pi++)
                LDSM_X4(bf[2 * pi][0], bf[2 * pi][1], bf[2 * pi + 1][0], bf[2 * pi + 1][1],
                        bAddr[pi] + bOff + kOff);
            #pragma unroll
            for (int mi = 0; mi < MI; mi++)
                #pragma unroll
                for (int ni = 0; ni < NF; ni++)
                    mma8(acc[mi][ni], af[mi], bf[ni]);
        }
    };

    loadGlobal(0);
    storeSmem(0);
    __syncthreads();
    const int kIters = Ktot / 32;
    for (int it = 0; it < kIters; ++it) {
        if (it + 1 < kIters) loadGlobal((it + 1) * 32);
        compute(it & 1);
        if (it + 1 < kIters) storeSmem((it + 1) & 1);
        __syncthreads();
    }

    #pragma unroll
    for (int mi = 0; mi < MI; mi++) {
        #pragma unroll
        for (int ni = 0; ni < NF; ni++) {
            int row = m0 + wM * (MI * 16) + mi * 16 + g;
            int col = n0 + wN * (BN / 2) + ni * 8 + 2 * tg;
            float v0 = acc[mi][ni][0], v1 = acc[mi][ni][1];
            float v2 = acc[mi][ni][2], v3 = acc[mi][ni][3];
            if (EPI == 0 || EPI == 1) {
                float bv0 = bias0[col], bv1 = bias0[col + 1];
                v0 += bv0; v1 += bv1; v2 += bv0; v3 += bv1;
            }
            if (EPI == 0) {
                v0 = f2tf_f(fmaxf(v0, 0.f)); v1 = f2tf_f(fmaxf(v1, 0.f));
                v2 = f2tf_f(fmaxf(v2, 0.f)); v3 = f2tf_f(fmaxf(v3, 0.f));
            }
            *(float2*)(out + (size_t)row * ldOut + col)       = make_float2(v0, v1);
            *(float2*)(out + (size_t)(row + 8) * ldOut + col) = make_float2(v2, v3);
        }
    }
}

// ---------------- merged dual GEMM: G2a (z=0) + G2bc (z=1) in one launch ----------------
// Same 256x128 occ-1 engine as R10/R14; per-z runtime selection of {W, Ktot, asel, out}.
// z=0: Grz = [X|Hr] @ Wrz^T  (K=1024, K-split A)
// z=1: NN  = [X@Win^T | Hr@Whn^T]  (K=512, A selected per n-block)
__global__ void __launch_bounds__(256, 1)
gemm_dual(const float* __restrict__ Xp, const float* __restrict__ Hrp,
          const float* __restrict__ Wrz, const float* __restrict__ Wnn,
          float* __restrict__ Grz, float* __restrict__ NN)
{
    constexpr int BMT = 256, BN = 128;
    constexpr int MI = 4, NF = 8, NP = 4, NA4 = 8, NB4 = 4;

    // per-z selection (dead after prologue; steady-state regs unchanged)
    const int  zz    = blockIdx.z;
    const int  asel  = zz;                       // 0: K-split, 1: per-n-block A
    const int  Ktot  = zz ? 512 : 1024;
    const int  ldW   = zz ? 512 : 1024;
    const float* W   = zz ? Wnn : Wrz;
    float*      out  = zz ? NN  : Grz;
    const int  ksplit = 512;

    extern __shared__ unsigned smem_u[];
    unsigned* As = smem_u;
    unsigned* Bs = smem_u + 2 * BMT * 36;

    const int tid  = threadIdx.x;
    const int lane = tid & 31;
    const int warp = tid >> 5;
    const int g    = lane >> 2;
    const int tg   = lane & 3;
    const int wM   = warp & 3;
    const int wN   = warp >> 2;
    const int m0   = blockIdx.y * BMT;
    const int n0   = blockIdx.x * BN;

    const unsigned sAbase = smem_u32p(As);
    const unsigned sBbase = smem_u32p(Bs);
    unsigned aAddr[MI], bAddr[NP];
    #pragma unroll
    for (int mi = 0; mi < MI; mi++) {
        int row = wM * 64 + mi * 16 + (lane & 15);
        int col = 4 * (lane >> 4);
        aAddr[mi] = sAbase + (unsigned)(row * 36 + col) * 4u;
    }
    #pragma unroll
    for (int pi = 0; pi < NP; pi++) {
        int row = wN * 64 + pi * 16 + (lane & 7) + 8 * (lane >> 4);
        int col = 4 * ((lane >> 3) & 1);
        bAddr[pi] = sBbase + (unsigned)(row * 36 + col) * 4u;
    }

    float acc[MI][NF][4];
    #pragma unroll
    for (int mi = 0; mi < MI; mi++)
        #pragma unroll
        for (int ni = 0; ni < NF; ni++)
            #pragma unroll
            for (int q = 0; q < 4; q++) acc[mi][ni][q] = 0.f;

    const int rb = tid >> 3;
    const int c4 = tid & 7;

    float4 pa[NA4], pb[NB4];
    auto loadGlobal = [&](int k0) {
        const float* Ap; int koff;
        if (asel)            { Ap = (n0 < ksplit) ? Xp : Hrp; koff = k0; }
        else if (k0 < ksplit){ Ap = Xp;  koff = k0; }
        else                 { Ap = Hrp; koff = k0 - ksplit; }
        #pragma unroll
        for (int i = 0; i < NA4; i++) {
            int r = rb + 32 * i;
            pa[i] = *(const float4*)(Ap + (size_t)(m0 + r) * 512 + koff + c4 * 4);
        }
        #pragma unroll
        for (int i = 0; i < NB4; i++) {
            int r = rb + 32 * i;
            pb[i] = *(const float4*)(W + (size_t)(n0 + r) * ldW + k0 + c4 * 4);
        }
    };
    auto storeSmem = [&](int buf) {
        unsigned* Ab = As + buf * BMT * 36;
        unsigned* Bb = Bs + buf * BN * 36;
        #pragma unroll
        for (int i = 0; i < NA4; i++) {
            int r = rb + 32 * i;
            *(uint4*)(Ab + r * 36 + c4 * 4) = *(const uint4*)&pa[i];
        }
        #pragma unroll
        for (int i = 0; i < NB4; i++) {
            int r = rb + 32 * i;
            *(uint4*)(Bb + r * 36 + c4 * 4) = *(const uint4*)&pb[i];
        }
    };

    auto compute = [&](int buf) {
        const unsigned aOff = (unsigned)(buf * BMT * 36) * 4u;
        const unsigned bOff = (unsigned)(buf * BN * 36) * 4u;
        #pragma unroll
        for (int ks = 0; ks < 4; ks++) {
            const unsigned kOff = (unsigned)ks * 32u;
            unsigned af[MI][4];
            #pragma unroll
            for (int mi = 0; mi < MI; mi++)
                LDSM_X4(af[mi][0], af[mi][1], af[mi][2], af[mi][3],
                        aAddr[mi] + aOff + kOff);
            unsigned bf[NF][2];
            #pragma unroll
            for (int pi = 0; pi < NP; pi++)
                LDSM_X4(bf[2 * pi][0], bf[2 * pi][1], bf[2 * pi + 1][0], bf[2 * pi + 1][1],
                        bAddr[pi] + bOff + kOff);
            #pragma unroll
            for (int mi = 0; mi < MI; mi++)
                #pragma unroll
                for (int ni = 0; ni < NF; ni++)
                    mma8(acc[mi][ni], af[mi], bf[ni]);
        }
    };

    loadGlobal(0);
    storeSmem(0);
    __syncthreads();
    const int kIters = Ktot / 32;
    for (int it = 0; it < kIters; ++it) {
        if (it + 1 < kIters) loadGlobal((it + 1) * 32);
        compute(it & 1);
        if (it + 1 < kIters) storeSmem((it + 1) & 1);
        __syncthreads();
    }

    // raw epilogue (EPI 3), ldOut = 1024 for both targets
    #pragma unroll
    for (int mi = 0; mi < MI; mi++) {
        #pragma unroll
        for (int ni = 0; ni < NF; ni++) {
            int row = m0 + wM * 64 + mi * 16 + g;
            int col = n0 + wN * 64 + ni * 8 + 2 * tg;
            *(float2*)(out + (size_t)row * 1024 + col)
                = make_float2(acc[mi][ni][0], acc[mi][ni][1]);
            *(float2*)(out + (size_t)(row + 8) * 1024 + col)
                = make_float2(acc[mi][ni][2], acc[mi][ni][3]);
        }
    }
}

// ---------------- host launcher ----------------
extern "C" void kernel_launch(void* const* d_in, const int* in_sizes, int n_in,
                              void* d_out, int out_size) {
    const float* inputs = (const float*)d_in[0];
    const float* hidden = (const float*)d_in[1];
    const float* W1     = (const float*)d_in[2];
    const float* b1     = (const float*)d_in[3];
    const float* W_ih   = (const float*)d_in[4];
    const float* W_hh   = (const float*)d_in[5];
    const float* b_ih   = (const float*)d_in[6];
    const float* b_hh   = (const float*)d_in[7];
    const float* W21    = (const float*)d_in[8];
    const float* b21    = (const float*)d_in[9];
    const float* W22    = (const float*)d_in[10];
    const float* b22    = (const float*)d_in[11];

    float* outQ = (float*)d_out;
    float* outH = (float*)d_out + (size_t)QSIZE;

    void *pX, *pHr, *pGrz, *pNN, *pWrz, *pWnn, *pW2, *pb2;
    cudaGetSymbolAddress(&pX,   g_X);
    cudaGetSymbolAddress(&pHr,  g_Hr);
    cudaGetSymbolAddress(&pGrz, g_Grz);
    cudaGetSymbolAddress(&pNN,  g_NN);
    cudaGetSymbolAddress(&pWrz, g_Wrz);
    cudaGetSymbolAddress(&pWnn, g_Wnn);
    cudaGetSymbolAddress(&pW2,  g_W2);
    cudaGetSymbolAddress(&pb2,  g_b2);

    const int smemBig  = (2 * 256 * 36 + 2 * 128 * 36) * 4;   // 110592
    const int smemHead = (2 * 128 * 36 + 2 *  64 * 36) * 4;   //  55296
    cudaFuncSetAttribute(gemm_tf32<256, 128, 0, true , 0, 1>, cudaFuncAttributeMaxDynamicSharedMemorySize, smemBig);
    cudaFuncSetAttribute(gemm_dual, cudaFuncAttributeMaxDynamicSharedMemorySize, smemBig);
    cudaFuncSetAttribute(gemm_tf32<128,  64, 1, false, 0, 2>, cudaFuncAttributeMaxDynamicSharedMemorySize, smemHead);

    // 0) pack + round split-gate weights; round hidden into g_Hr
    pack_kernel<<<(1024 * 1024) / 256, 256>>>(W_ih, W_hh, W21, W22, b21, b22);
    roundH_kernel<<<(NB * 128) / 256, 256>>>(hidden);

    // 1) X = round(relu(inputs @ W1^T + b1))   [B,512], K=256  (R14 config)
    gemm_tf32<256, 128, 0, true, 0, 1><<<dim3(4, NB / 256), 256, smemBig>>>(
        inputs, inputs, IN2, IN2, IN2,
        W1, IN2, b1, (float*)pX, H2);

    // 2) MERGED: z=0 -> Grz = [X|Hr]@Wrz^T (K=1024); z=1 -> NN = [X@Win^T | Hr@Whn^T] (K=512)
    gemm_dual<<<dim3(8, NB / 256, 2), 256, smemBig>>>(
        (const float*)pX, (const float*)pHr,
        (const float*)pWrz, (const float*)pWnn,
        (float*)pGrz, (float*)pNN);

    // 2d) combine gates -> h (rounded) into outH (reads raw hidden for h_in)
    gru_combine<<<(NB * 256) / 256, 256>>>(
        (const float*)pGrz, (const float*)pNN, hidden, b_ih, b_hh, outH);

    // 3) q = h @ [W21;W22]^T + b, interleaved == row-major [B,64]  (128-tile, 2 CTA/SM)
    gemm_tf32<128, 64, 1, false, 0, 2><<<dim3(1, NB / 128), 256, smemHead>>>(
        outH, outH, H2, H2, H2,
        (const float*)pW2, H2, (const float*)pb2, outQ, 64);
}